// round 10
// baseline (speedup 1.0000x reference)
#include <cuda_runtime.h>
#include <cuda_bf16.h>
#include <cstdint>
#include <cstddef>

// ---------------------------------------------------------------------------
// QLoRABigNet, mma.sync path (tcgen05 unavailable at compute_103 PTX target).
// 18 layers of y = x @ W_eff^T + bias (+relu / +residual / LN).
// W_eff = dequant_int4 + lora_b@lora_a precomputed; split-bf16 3-MMA numerics.
// R10: K=32 chunks, 2-stage mbarrier ring (halves per-chunk fixed costs vs
//      R9's K16x4); LayerNorm writes only bf16 hi/lo pair (residual read as
//      hi+lo in the mode-1 epilogue) -> LN traffic halved.
// ---------------------------------------------------------------------------

#define NL    18
#define DIMV  1024
#define BV    32768
#define NGRP  64

#define TM 128
#define TN 128
#define KC32 32
#define NC2 (DIMV / KC32)        // 32 chunks
#define NTHR 256

#define ROWB 80                  // 64B data + 16B pad, conflict-free ldsm
#define OFF_AHI 0
#define OFF_ALO 10240            // 128*80
#define OFF_BHI 20480
#define OFF_BLO 30720
#define STAGE_BYTES 40960
#define NSTAGE 2
#define MB_BASE (NSTAGE * STAGE_BYTES)      // 81920
#define SMEM_TOTAL (MB_BASE + 128)          // 82048 -> 2 CTAs/SM

// ---- scratch (device globals: allocation-free contract) --------------------
__device__ __nv_bfloat16 g_Whi[(size_t)NL * DIMV * DIMV];
__device__ __nv_bfloat16 g_Wlo[(size_t)NL * DIMV * DIMV];
__device__ __nv_bfloat16 g_ahi0[(size_t)BV * DIMV];
__device__ __nv_bfloat16 g_alo0[(size_t)BV * DIMV];
__device__ __nv_bfloat16 g_ahi1[(size_t)BV * DIMV];
__device__ __nv_bfloat16 g_alo1[(size_t)BV * DIMV];
__device__ float         g_ybuf[(size_t)BV * DIMV];
__device__ float         g_h[(size_t)BV * DIMV];   // carved: Hhi | Hlo (bf16)

// ---------------------------------------------------------------------------
// PTX helpers
// ---------------------------------------------------------------------------
__device__ __forceinline__ void ldsm4(uint32_t* r, uint32_t a) {
    asm volatile("ldmatrix.sync.aligned.m8n8.x4.shared.b16 {%0,%1,%2,%3}, [%4];\n"
                 : "=r"(r[0]), "=r"(r[1]), "=r"(r[2]), "=r"(r[3]) : "r"(a));
}
__device__ __forceinline__ void mma16816(float* c, const uint32_t* a, const uint32_t* b) {
    asm volatile(
        "mma.sync.aligned.m16n8k16.row.col.f32.bf16.bf16.f32 "
        "{%0,%1,%2,%3}, {%4,%5,%6,%7}, {%8,%9}, {%0,%1,%2,%3};\n"
        : "+f"(c[0]), "+f"(c[1]), "+f"(c[2]), "+f"(c[3])
        : "r"(a[0]), "r"(a[1]), "r"(a[2]), "r"(a[3]), "r"(b[0]), "r"(b[1]));
}
__device__ __forceinline__ void cpa16(uint32_t dst, const void* src) {
    asm volatile("cp.async.cg.shared.global [%0], [%1], 16;" :: "r"(dst), "l"(src));
}
__device__ __forceinline__ void mbar_init(uint32_t addr, uint32_t cnt) {
    asm volatile("mbarrier.init.shared.b64 [%0], %1;" :: "r"(addr), "r"(cnt) : "memory");
}
__device__ __forceinline__ void mbar_arrive(uint32_t addr) {
    asm volatile("mbarrier.arrive.shared.b64 _, [%0];" :: "r"(addr) : "memory");
}
__device__ __forceinline__ void cp_arrive_noinc(uint32_t addr) {
    asm volatile("cp.async.mbarrier.arrive.noinc.shared.b64 [%0];" :: "r"(addr) : "memory");
}
__device__ __forceinline__ void mbar_wait(uint32_t addr, uint32_t parity) {
    asm volatile(
        "{\n .reg .pred P;\n"
        "W%=:\n mbarrier.try_wait.parity.acquire.cta.shared::cta.b64 P, [%0], %1, 0x989680;\n"
        " @P bra D%=;\n bra W%=;\nD%=:\n}"
        :: "r"(addr), "r"(parity) : "memory");
}

// ---------------------------------------------------------------------------
// Prepass: W_eff = qw*scale + B@A, split bf16 hi/lo. (validated R3/R5-R9)
// ---------------------------------------------------------------------------
__global__ __launch_bounds__(256) void prep_w_kernel(
    const int* __restrict__ qw, const float* __restrict__ sc,
    const float* __restrict__ la, const float* __restrict__ lb,
    __nv_bfloat16* __restrict__ Whi, __nv_bfloat16* __restrict__ Wlo)
{
    int l  = blockIdx.z;
    int o0 = blockIdx.y * 64;
    int k0 = blockIdx.x * 64;
    int tid = threadIdx.x;

    __shared__ float sLb[64][32];
    __shared__ float sLa[32][64];

    const float* lbp = lb + (size_t)l * DIMV * 32;
    const float* lap = la + (size_t)l * 32 * DIMV;

#pragma unroll
    for (int i = 0; i < 8; i++) {
        int off = tid + i * 256;
        int o = off >> 5, r = off & 31;
        sLb[o][r] = lbp[(size_t)(o0 + o) * 32 + r];
        int r2 = off >> 6, k = off & 63;
        sLa[r2][k] = lap[(size_t)r2 * DIMV + k0 + k];
    }
    __syncthreads();

    int to = tid >> 4, tk = tid & 15;
    float m[4][4];
#pragma unroll
    for (int i = 0; i < 4; i++)
#pragma unroll
        for (int j = 0; j < 4; j++) m[i][j] = 0.f;

#pragma unroll 8
    for (int r = 0; r < 32; r++) {
        float av[4], bv[4];
#pragma unroll
        for (int j = 0; j < 4; j++) av[j] = sLa[r][tk * 4 + j];
#pragma unroll
        for (int i = 0; i < 4; i++) bv[i] = sLb[to * 4 + i][r];
#pragma unroll
        for (int i = 0; i < 4; i++)
#pragma unroll
            for (int j = 0; j < 4; j++) m[i][j] += bv[i] * av[j];
    }

#pragma unroll
    for (int i = 0; i < 4; i++) {
        int o = o0 + to * 4 + i;
        const int*   qrow = qw + ((size_t)l * DIMV + o) * DIMV + k0;
        const float* srow = sc + ((size_t)l * DIMV + o) * NGRP;
#pragma unroll
        for (int j = 0; j < 4; j++) {
            int k = k0 + tk * 4 + j;
            float wv = (float)qrow[tk * 4 + j] * srow[k >> 4] + m[i][j];
            size_t idx = ((size_t)l * DIMV + o) * DIMV + k;
            __nv_bfloat16 h = __float2bfloat16(wv);
            Whi[idx] = h;
            Wlo[idx] = __float2bfloat16(wv - __bfloat162float(h));
        }
    }
}

__global__ __launch_bounds__(256) void split_x_kernel(
    const float* __restrict__ x, __nv_bfloat16* __restrict__ hi,
    __nv_bfloat16* __restrict__ lo)
{
    size_t i = (size_t)blockIdx.x * 256 + threadIdx.x;
    float v = x[i];
    __nv_bfloat16 h = __float2bfloat16(v);
    hi[i] = h;
    lo[i] = __float2bfloat16(v - __bfloat162float(h));
}

// ---------------------------------------------------------------------------
// GEMM: C[BV,DIMV] = X @ W^T. grid (8, 256), 256 threads, 8 warps (2x4),
// warp tile 64x32. 2-stage mbarrier ring over K=32 chunks, 2 CTAs/SM.
// mode 0: out = relu(acc+bias) -> bf16 hi/lo pair
// mode 1: out = acc+bias+res -> fp32; res = hinf (fp32) if non-null,
//         else hi+lo from (hinh, hinl) bf16 pair.
// ---------------------------------------------------------------------------
__device__ __forceinline__ void load_stage(
    uint32_t sb, int s, int c, int tid, int m0, int n0,
    const __nv_bfloat16* __restrict__ Xhi, const __nv_bfloat16* __restrict__ Xlo,
    const __nv_bfloat16* __restrict__ Whi, const __nv_bfloat16* __restrict__ Wlo)
{
    const uint32_t st = sb + (uint32_t)s * STAGE_BYTES;
    const int kbase = c * KC32;
#pragma unroll
    for (int i = 0; i < 2; i++) {
        int idx = i * NTHR + tid;
        int row = idx >> 2, seg = idx & 3;
        uint32_t off = (uint32_t)(row * ROWB + seg * 16);
        const size_t ga = (size_t)(m0 + row) * DIMV + kbase + seg * 8;
        cpa16(st + OFF_AHI + off, Xhi + ga);
        cpa16(st + OFF_ALO + off, Xlo + ga);
        const size_t gb = (size_t)(n0 + row) * DIMV + kbase + seg * 8;
        cpa16(st + OFF_BHI + off, Whi + gb);
        cpa16(st + OFF_BLO + off, Wlo + gb);
    }
    // signal full[s] when this thread's 8 copies land (expected count = 256)
    cp_arrive_noinc(sb + MB_BASE + (uint32_t)s * 16);
}

__global__ __launch_bounds__(NTHR, 2) void gemm_kernel(
    const __nv_bfloat16* __restrict__ Xhi, const __nv_bfloat16* __restrict__ Xlo,
    const __nv_bfloat16* __restrict__ Whi, const __nv_bfloat16* __restrict__ Wlo,
    const float* __restrict__ bias, int mode,
    const float* __restrict__ hinf,
    const __nv_bfloat16* __restrict__ hinh, const __nv_bfloat16* __restrict__ hinl,
    float* __restrict__ fout,
    __nv_bfloat16* __restrict__ Ohi, __nv_bfloat16* __restrict__ Olo)
{
    extern __shared__ __align__(128) char smem[];
    const uint32_t sb = (uint32_t)__cvta_generic_to_shared(smem);

    const int tid = threadIdx.x, warp = tid >> 5, lane = tid & 31;
    const int wm = warp >> 2, wn = warp & 3;         // 2 x 4 warp grid, 64x32 tile
    const int m0 = blockIdx.y * TM, n0 = blockIdx.x * TN;

    // barriers: full[s] at MB_BASE + s*16, empty[s] at +8
    if (tid == 0) {
#pragma unroll
        for (int s = 0; s < NSTAGE; s++) {
            mbar_init(sb + MB_BASE + s * 16, NTHR);  // full: one noinc-arrive per thread
            mbar_init(sb + MB_BASE + s * 16 + 8, 8); // empty: one arrive per warp
        }
    }
    __syncthreads();

    // ldmatrix per-lane addressing (bytes, relative to stage base)
    const int mi = lane >> 3, rr = lane & 7;
    const uint32_t a_base = (uint32_t)((wm * 64 + (mi & 1) * 8 + rr) * ROWB
                                       + ((mi >> 1) * 8) * 2);
    const uint32_t b_base = (uint32_t)((wn * 32 + ((lane >> 4) << 3) + (lane & 7)) * ROWB
                                       + (((lane >> 3) & 1) * 8) * 2);

    // prologue: produce chunk 0 into stage 0
    load_stage(sb, 0, 0, tid, m0, n0, Xhi, Xlo, Whi, Wlo);

    float acc[4][4][4];
#pragma unroll
    for (int i = 0; i < 4; i++)
#pragma unroll
        for (int j = 0; j < 4; j++)
#pragma unroll
            for (int q = 0; q < 4; q++) acc[i][j][q] = 0.f;

#pragma unroll 2
    for (int c = 0; c < NC2; ++c) {
        // produce chunk c+1 into stage (c+1)&1 (WAR-gated on chunk c-1 consumed)
        const int pc = c + 1;
        if (pc < NC2) {
            const int ps = pc & 1, pj = pc >> 1;
            if (pc >= 2)
                mbar_wait(sb + MB_BASE + (uint32_t)ps * 16 + 8, (pj - 1) & 1);
            load_stage(sb, ps, pc, tid, m0, n0, Xhi, Xlo, Whi, Wlo);
        }

        // consume chunk c
        const int s = c & 1, j = c >> 1;
        mbar_wait(sb + MB_BASE + (uint32_t)s * 16, j & 1);
        const uint32_t st = sb + (uint32_t)s * STAGE_BYTES;

#pragma unroll
        for (int ks = 0; ks < 2; ks++) {
            const uint32_t ko = ks * 32;            // 16 elems * 2B

            uint32_t wh[8], wl[8];
#pragma unroll
            for (int nfp = 0; nfp < 2; nfp++) {
                uint32_t bo = b_base + (uint32_t)(nfp * 16 * ROWB) + ko;
                ldsm4(wh + 4 * nfp, st + OFF_BHI + bo);
                ldsm4(wl + 4 * nfp, st + OFF_BLO + bo);
            }
            uint32_t fxh[4][4], fxl[4][4];
#pragma unroll
            for (int mf = 0; mf < 4; mf++) {
                uint32_t ao = a_base + (uint32_t)(mf * 16 * ROWB) + ko;
                ldsm4(fxh[mf], st + OFF_AHI + ao);
                ldsm4(fxl[mf], st + OFF_ALO + ao);
            }
            // after the LAST ldsm batch of this chunk, buffer is reusable
            if (ks == 1 && lane == 0)
                mbar_arrive(sb + MB_BASE + (uint32_t)s * 16 + 8);

            // term-major: 16 independent HMMAs per pass
#pragma unroll
            for (int mf = 0; mf < 4; mf++)
#pragma unroll
                for (int nf = 0; nf < 4; nf++)
                    mma16816(acc[mf][nf], fxh[mf], wh + 2 * nf);
#pragma unroll
            for (int mf = 0; mf < 4; mf++)
#pragma unroll
                for (int nf = 0; nf < 4; nf++)
                    mma16816(acc[mf][nf], fxl[mf], wh + 2 * nf);
#pragma unroll
            for (int mf = 0; mf < 4; mf++)
#pragma unroll
                for (int nf = 0; nf < 4; nf++)
                    mma16816(acc[mf][nf], fxh[mf], wl + 2 * nf);
        }
    }

    // epilogue
#pragma unroll
    for (int mf = 0; mf < 4; mf++) {
#pragma unroll
        for (int nf = 0; nf < 4; nf++) {
            const float* c = acc[mf][nf];
            int row0 = m0 + wm * 64 + mf * 16 + (lane >> 2);
            int row1 = row0 + 8;
            int n = n0 + wn * 32 + nf * 8 + 2 * (lane & 3);
            float bn0 = bias[n], bn1 = bias[n + 1];
            size_t o0 = (size_t)row0 * DIMV + n;
            size_t o1 = (size_t)row1 * DIMV + n;
            if (mode == 0) {
                float v00 = fmaxf(c[0] + bn0, 0.f), v01 = fmaxf(c[1] + bn1, 0.f);
                float v10 = fmaxf(c[2] + bn0, 0.f), v11 = fmaxf(c[3] + bn1, 0.f);
                __nv_bfloat162 h2, l2;
                h2.x = __float2bfloat16(v00); l2.x = __float2bfloat16(v00 - __bfloat162float(h2.x));
                h2.y = __float2bfloat16(v01); l2.y = __float2bfloat16(v01 - __bfloat162float(h2.y));
                *(__nv_bfloat162*)(Ohi + o0) = h2;
                *(__nv_bfloat162*)(Olo + o0) = l2;
                h2.x = __float2bfloat16(v10); l2.x = __float2bfloat16(v10 - __bfloat162float(h2.x));
                h2.y = __float2bfloat16(v11); l2.y = __float2bfloat16(v11 - __bfloat162float(h2.y));
                *(__nv_bfloat162*)(Ohi + o1) = h2;
                *(__nv_bfloat162*)(Olo + o1) = l2;
            } else {
                float2 hv0, hv1;
                if (hinf) {
                    hv0 = *(const float2*)(hinf + o0);
                    hv1 = *(const float2*)(hinf + o1);
                } else {
                    __nv_bfloat162 h0 = *(const __nv_bfloat162*)(hinh + o0);
                    __nv_bfloat162 l0 = *(const __nv_bfloat162*)(hinl + o0);
                    __nv_bfloat162 h1 = *(const __nv_bfloat162*)(hinh + o1);
                    __nv_bfloat162 l1 = *(const __nv_bfloat162*)(hinl + o1);
                    hv0.x = __bfloat162float(h0.x) + __bfloat162float(l0.x);
                    hv0.y = __bfloat162float(h0.y) + __bfloat162float(l0.y);
                    hv1.x = __bfloat162float(h1.x) + __bfloat162float(l1.x);
                    hv1.y = __bfloat162float(h1.y) + __bfloat162float(l1.y);
                }
                float2 r0v; r0v.x = c[0] + bn0 + hv0.x; r0v.y = c[1] + bn1 + hv0.y;
                float2 r1v; r1v.x = c[2] + bn0 + hv1.x; r1v.y = c[3] + bn1 + hv1.y;
                *(float2*)(fout + o0) = r0v;
                *(float2*)(fout + o1) = r1v;
            }
        }
    }
}

// ---------------------------------------------------------------------------
// LayerNorm: reads fp32 t, writes ONLY the bf16 hi/lo pair (activation AND
// residual source for layer 3k+2 -> no fp32 hout stream).
// ---------------------------------------------------------------------------
__global__ __launch_bounds__(256) void ln_kernel(
    const float* __restrict__ t, const float* __restrict__ g,
    const float* __restrict__ bb,
    __nv_bfloat16* __restrict__ Ohi, __nv_bfloat16* __restrict__ Olo)
{
    int row = blockIdx.x;
    int tid = threadIdx.x;
    const float* tr = t + (size_t)row * DIMV;

    float v[4];
#pragma unroll
    for (int i = 0; i < 4; i++) v[i] = tr[tid + 256 * i];

    float s = v[0] + v[1] + v[2] + v[3];
#pragma unroll
    for (int o = 16; o > 0; o >>= 1) s += __shfl_xor_sync(0xffffffffu, s, o);

    __shared__ float red[8];
    int w = tid >> 5, ln = tid & 31;
    if (ln == 0) red[w] = s;
    __syncthreads();
    float tot = 0.f;
#pragma unroll
    for (int i = 0; i < 8; i++) tot += red[i];
    float mu = tot * (1.0f / 1024.0f);

    float sq = 0.f;
#pragma unroll
    for (int i = 0; i < 4; i++) { float d = v[i] - mu; sq += d * d; }
#pragma unroll
    for (int o = 16; o > 0; o >>= 1) sq += __shfl_xor_sync(0xffffffffu, sq, o);
    __syncthreads();
    if (ln == 0) red[w] = sq;
    __syncthreads();
    float vtot = 0.f;
#pragma unroll
    for (int i = 0; i < 8; i++) vtot += red[i];
    float rs = rsqrtf(vtot * (1.0f / 1024.0f) + 1e-5f);

#pragma unroll
    for (int i = 0; i < 4; i++) {
        int col = tid + 256 * i;
        float o = (v[i] - mu) * rs * g[col] + bb[col];
        size_t idx = (size_t)row * DIMV + col;
        __nv_bfloat16 h = __float2bfloat16(o);
        Ohi[idx] = h;
        Olo[idx] = __float2bfloat16(o - __bfloat162float(h));
    }
}

// ---------------------------------------------------------------------------
// Host
// ---------------------------------------------------------------------------
extern "C" void kernel_launch(void* const* d_in, const int* in_sizes, int n_in,
                              void* d_out, int out_size)
{
    const float* x      = (const float*)d_in[0];
    const int*   qw     = (const int*)d_in[1];
    const float* scales = (const float*)d_in[2];
    const float* bias   = (const float*)d_in[3];
    const float* la     = (const float*)d_in[4];
    const float* lb     = (const float*)d_in[5];
    const float* lng    = (const float*)d_in[6];
    const float* lnb    = (const float*)d_in[7];
    float* out = (float*)d_out;

    void* p;
    cudaGetSymbolAddress(&p, g_Whi);  __nv_bfloat16* Whi  = (__nv_bfloat16*)p;
    cudaGetSymbolAddress(&p, g_Wlo);  __nv_bfloat16* Wlo  = (__nv_bfloat16*)p;
    cudaGetSymbolAddress(&p, g_ahi0); __nv_bfloat16* Ahi0 = (__nv_bfloat16*)p;
    cudaGetSymbolAddress(&p, g_alo0); __nv_bfloat16* Alo0 = (__nv_bfloat16*)p;
    cudaGetSymbolAddress(&p, g_ahi1); __nv_bfloat16* Ahi1 = (__nv_bfloat16*)p;
    cudaGetSymbolAddress(&p, g_alo1); __nv_bfloat16* Alo1 = (__nv_bfloat16*)p;
    cudaGetSymbolAddress(&p, g_ybuf); float* Ybuf = (float*)p;
    cudaGetSymbolAddress(&p, g_h);
    __nv_bfloat16* Hhi = (__nv_bfloat16*)p;                       // first half of g_h
    __nv_bfloat16* Hlo = (__nv_bfloat16*)p + (size_t)BV * DIMV;   // second half

    cudaFuncSetAttribute(gemm_kernel,
                         cudaFuncAttributeMaxDynamicSharedMemorySize, SMEM_TOTAL);

    prep_w_kernel<<<dim3(16, 16, NL), 256>>>(qw, scales, la, lb, Whi, Wlo);
    // x split goes into the H pair (input of layer 0)
    split_x_kernel<<<(BV * DIMV) / 256, 256>>>(x, Hhi, Hlo);

    for (int l = 0; l < NL; l++) {
        const __nv_bfloat16* wh = Whi + (size_t)l * DIMV * DIMV;
        const __nv_bfloat16* wl = Wlo + (size_t)l * DIMV * DIMV;
        const float* bl = bias + (size_t)l * DIMV;
        const int j = l % 3;

        // layer inputs: 3k <- H pair; 3k+1 <- act0; 3k+2 <- act1
        const __nv_bfloat16* xhi = (j == 0) ? Hhi : (j == 1 ? Ahi0 : Ahi1);
        const __nv_bfloat16* xlo = (j == 0) ? Hlo : (j == 1 ? Alo0 : Alo1);

        if (j != 2) {
            __nv_bfloat16* ohi = (j == 0) ? Ahi0 : Ahi1;
            __nv_bfloat16* olo = (j == 0) ? Alo0 : Alo1;
            gemm_kernel<<<dim3(DIMV / TN, BV / TM), NTHR, SMEM_TOTAL>>>(
                xhi, xlo, wh, wl, bl, 0,
                nullptr, nullptr, nullptr, nullptr, ohi, olo);
        } else {
            // residual: block 0 uses original fp32 x; later blocks use H pair
            const float* hinf = (l == 2) ? x : nullptr;
            const __nv_bfloat16* hinh = (l == 2) ? nullptr : Hhi;
            const __nv_bfloat16* hinl = (l == 2) ? nullptr : Hlo;
            float* fo = (l == NL - 1) ? out : Ybuf;
            gemm_kernel<<<dim3(DIMV / TN, BV / TM), NTHR, SMEM_TOTAL>>>(
                xhi, xlo, wh, wl, bl, 1,
                hinf, hinh, hinl, fo, nullptr, nullptr);
            if (l != NL - 1) {
                int blk = l / 3;
                ln_kernel<<<BV, 256>>>(Ybuf, lng + (size_t)blk * DIMV,
                                       lnb + (size_t)blk * DIMV, Hhi, Hlo);
            }
        }
    }
}

// round 11
// speedup vs baseline: 1.0266x; 1.0266x over previous
#include <cuda_runtime.h>
#include <cuda_bf16.h>
#include <cstdint>
#include <cstddef>

// ---------------------------------------------------------------------------
// QLoRABigNet, mma.sync path (tcgen05 unavailable at compute_103 PTX target).
// 18 layers of y = x @ W_eff^T + bias (+relu / +residual / LN).
// W_eff = dequant_int4 + lora_b@lora_a precomputed; split-bf16 3-MMA numerics.
// R11: R9's GEMM verbatim (K16 x 4-stage mbarrier ring, produce-ahead-2,
//      best measured: 508us/layer, tensor 67.2%) + R10's LN fusion
//      (bf16 H-pair residual, no fp32 hout stream; LN traffic halved).
// ---------------------------------------------------------------------------

#define NL    18
#define DIMV  1024
#define BV    32768
#define NGRP  64

#define TM 128
#define TN 128
#define KC16 16
#define NC (DIMV / KC16)         // 64 chunks
#define NSTAGE 4
#define NTHR 256

#define ROWB 48                  // 32B data + 16B pad, conflict-free ldsm
#define OFF_AHI 0
#define OFF_ALO 6144             // 128*48
#define OFF_BHI 12288
#define OFF_BLO 18432
#define STAGE_BYTES 24576
#define MB_BASE (NSTAGE * STAGE_BYTES)      // 98304
#define SMEM_TOTAL (MB_BASE + 128)          // 98432 -> 2 CTAs/SM

// ---- scratch (device globals: allocation-free contract) --------------------
__device__ __nv_bfloat16 g_Whi[(size_t)NL * DIMV * DIMV];
__device__ __nv_bfloat16 g_Wlo[(size_t)NL * DIMV * DIMV];
__device__ __nv_bfloat16 g_ahi0[(size_t)BV * DIMV];
__device__ __nv_bfloat16 g_alo0[(size_t)BV * DIMV];
__device__ __nv_bfloat16 g_ahi1[(size_t)BV * DIMV];
__device__ __nv_bfloat16 g_alo1[(size_t)BV * DIMV];
__device__ float         g_ybuf[(size_t)BV * DIMV];
__device__ float         g_h[(size_t)BV * DIMV];   // carved: Hhi | Hlo (bf16)

// ---------------------------------------------------------------------------
// PTX helpers
// ---------------------------------------------------------------------------
__device__ __forceinline__ void ldsm4(uint32_t* r, uint32_t a) {
    asm volatile("ldmatrix.sync.aligned.m8n8.x4.shared.b16 {%0,%1,%2,%3}, [%4];\n"
                 : "=r"(r[0]), "=r"(r[1]), "=r"(r[2]), "=r"(r[3]) : "r"(a));
}
__device__ __forceinline__ void mma16816(float* c, const uint32_t* a, const uint32_t* b) {
    asm volatile(
        "mma.sync.aligned.m16n8k16.row.col.f32.bf16.bf16.f32 "
        "{%0,%1,%2,%3}, {%4,%5,%6,%7}, {%8,%9}, {%0,%1,%2,%3};\n"
        : "+f"(c[0]), "+f"(c[1]), "+f"(c[2]), "+f"(c[3])
        : "r"(a[0]), "r"(a[1]), "r"(a[2]), "r"(a[3]), "r"(b[0]), "r"(b[1]));
}
__device__ __forceinline__ void cpa16(uint32_t dst, const void* src) {
    asm volatile("cp.async.cg.shared.global [%0], [%1], 16;" :: "r"(dst), "l"(src));
}
__device__ __forceinline__ void mbar_init(uint32_t addr, uint32_t cnt) {
    asm volatile("mbarrier.init.shared.b64 [%0], %1;" :: "r"(addr), "r"(cnt) : "memory");
}
__device__ __forceinline__ void mbar_arrive(uint32_t addr) {
    asm volatile("mbarrier.arrive.shared.b64 _, [%0];" :: "r"(addr) : "memory");
}
__device__ __forceinline__ void cp_arrive_noinc(uint32_t addr) {
    asm volatile("cp.async.mbarrier.arrive.noinc.shared.b64 [%0];" :: "r"(addr) : "memory");
}
__device__ __forceinline__ void mbar_wait(uint32_t addr, uint32_t parity) {
    asm volatile(
        "{\n .reg .pred P;\n"
        "W%=:\n mbarrier.try_wait.parity.acquire.cta.shared::cta.b64 P, [%0], %1, 0x989680;\n"
        " @P bra D%=;\n bra W%=;\nD%=:\n}"
        :: "r"(addr), "r"(parity) : "memory");
}

// ---------------------------------------------------------------------------
// Prepass: W_eff = qw*scale + B@A, split bf16 hi/lo. (validated R3/R5-R10)
// ---------------------------------------------------------------------------
__global__ __launch_bounds__(256) void prep_w_kernel(
    const int* __restrict__ qw, const float* __restrict__ sc,
    const float* __restrict__ la, const float* __restrict__ lb,
    __nv_bfloat16* __restrict__ Whi, __nv_bfloat16* __restrict__ Wlo)
{
    int l  = blockIdx.z;
    int o0 = blockIdx.y * 64;
    int k0 = blockIdx.x * 64;
    int tid = threadIdx.x;

    __shared__ float sLb[64][32];
    __shared__ float sLa[32][64];

    const float* lbp = lb + (size_t)l * DIMV * 32;
    const float* lap = la + (size_t)l * 32 * DIMV;

#pragma unroll
    for (int i = 0; i < 8; i++) {
        int off = tid + i * 256;
        int o = off >> 5, r = off & 31;
        sLb[o][r] = lbp[(size_t)(o0 + o) * 32 + r];
        int r2 = off >> 6, k = off & 63;
        sLa[r2][k] = lap[(size_t)r2 * DIMV + k0 + k];
    }
    __syncthreads();

    int to = tid >> 4, tk = tid & 15;
    float m[4][4];
#pragma unroll
    for (int i = 0; i < 4; i++)
#pragma unroll
        for (int j = 0; j < 4; j++) m[i][j] = 0.f;

#pragma unroll 8
    for (int r = 0; r < 32; r++) {
        float av[4], bv[4];
#pragma unroll
        for (int j = 0; j < 4; j++) av[j] = sLa[r][tk * 4 + j];
#pragma unroll
        for (int i = 0; i < 4; i++) bv[i] = sLb[to * 4 + i][r];
#pragma unroll
        for (int i = 0; i < 4; i++)
#pragma unroll
            for (int j = 0; j < 4; j++) m[i][j] += bv[i] * av[j];
    }

#pragma unroll
    for (int i = 0; i < 4; i++) {
        int o = o0 + to * 4 + i;
        const int*   qrow = qw + ((size_t)l * DIMV + o) * DIMV + k0;
        const float* srow = sc + ((size_t)l * DIMV + o) * NGRP;
#pragma unroll
        for (int j = 0; j < 4; j++) {
            int k = k0 + tk * 4 + j;
            float wv = (float)qrow[tk * 4 + j] * srow[k >> 4] + m[i][j];
            size_t idx = ((size_t)l * DIMV + o) * DIMV + k;
            __nv_bfloat16 h = __float2bfloat16(wv);
            Whi[idx] = h;
            Wlo[idx] = __float2bfloat16(wv - __bfloat162float(h));
        }
    }
}

__global__ __launch_bounds__(256) void split_x_kernel(
    const float* __restrict__ x, __nv_bfloat16* __restrict__ hi,
    __nv_bfloat16* __restrict__ lo)
{
    size_t i = (size_t)blockIdx.x * 256 + threadIdx.x;
    float v = x[i];
    __nv_bfloat16 h = __float2bfloat16(v);
    hi[i] = h;
    lo[i] = __float2bfloat16(v - __bfloat162float(h));
}

// ---------------------------------------------------------------------------
// GEMM: C[BV,DIMV] = X @ W^T. grid (8, 256), 256 threads, 8 warps (2x4),
// warp tile 64x32. mbarrier 4-stage ring over K=16 chunks, 2 CTAs/SM.
// mode 0: out = relu(acc+bias) -> bf16 hi/lo pair
// mode 1: out = acc+bias+res -> fp32; res = hinf (fp32) if non-null,
//         else hi+lo from (hinh, hinl) bf16 pair.
// ---------------------------------------------------------------------------
__device__ __forceinline__ void load_stage(
    uint32_t sb, int s, int c, int tid, int m0, int n0,
    const __nv_bfloat16* __restrict__ Xhi, const __nv_bfloat16* __restrict__ Xlo,
    const __nv_bfloat16* __restrict__ Whi, const __nv_bfloat16* __restrict__ Wlo)
{
    const uint32_t st = sb + (uint32_t)s * STAGE_BYTES;
    const int kbase = c * KC16;
    const int row = tid >> 1, seg = tid & 1;
    const uint32_t off = (uint32_t)(row * ROWB + seg * 16);
    const size_t ga = (size_t)(m0 + row) * DIMV + kbase + seg * 8;
    cpa16(st + OFF_AHI + off, Xhi + ga);
    cpa16(st + OFF_ALO + off, Xlo + ga);
    const size_t gb = (size_t)(n0 + row) * DIMV + kbase + seg * 8;
    cpa16(st + OFF_BHI + off, Whi + gb);
    cpa16(st + OFF_BLO + off, Wlo + gb);
    // signal full[s] when this thread's copies land (expected count = 256)
    cp_arrive_noinc(sb + MB_BASE + (uint32_t)s * 16);
}

__global__ __launch_bounds__(NTHR, 2) void gemm_kernel(
    const __nv_bfloat16* __restrict__ Xhi, const __nv_bfloat16* __restrict__ Xlo,
    const __nv_bfloat16* __restrict__ Whi, const __nv_bfloat16* __restrict__ Wlo,
    const float* __restrict__ bias, int mode,
    const float* __restrict__ hinf,
    const __nv_bfloat16* __restrict__ hinh, const __nv_bfloat16* __restrict__ hinl,
    float* __restrict__ fout,
    __nv_bfloat16* __restrict__ Ohi, __nv_bfloat16* __restrict__ Olo)
{
    extern __shared__ __align__(128) char smem[];
    const uint32_t sb = (uint32_t)__cvta_generic_to_shared(smem);

    const int tid = threadIdx.x, warp = tid >> 5, lane = tid & 31;
    const int wm = warp >> 2, wn = warp & 3;         // 2 x 4 warp grid, 64x32 tile
    const int m0 = blockIdx.y * TM, n0 = blockIdx.x * TN;

    // barriers: full[s] at MB_BASE + s*16, empty[s] at +8
    if (tid == 0) {
#pragma unroll
        for (int s = 0; s < NSTAGE; s++) {
            mbar_init(sb + MB_BASE + s * 16, NTHR);  // full: one noinc-arrive per thread
            mbar_init(sb + MB_BASE + s * 16 + 8, 8); // empty: one arrive per warp
        }
    }
    __syncthreads();

    // ldmatrix per-lane addressing (bytes, relative to stage base)
    const int mi = lane >> 3, rr = lane & 7;
    const uint32_t a_base = (uint32_t)((wm * 64 + (mi & 1) * 8 + rr) * ROWB
                                       + ((mi >> 1) * 8) * 2);
    const uint32_t b_base = (uint32_t)((wn * 32 + ((lane >> 4) << 3) + (lane & 7)) * ROWB
                                       + (((lane >> 3) & 1) * 8) * 2);

    // prologue: produce chunks 0,1 into stages 0,1 (produce-ahead distance 2)
    load_stage(sb, 0, 0, tid, m0, n0, Xhi, Xlo, Whi, Wlo);
    load_stage(sb, 1, 1, tid, m0, n0, Xhi, Xlo, Whi, Wlo);

    float acc[4][4][4];
#pragma unroll
    for (int i = 0; i < 4; i++)
#pragma unroll
        for (int j = 0; j < 4; j++)
#pragma unroll
            for (int q = 0; q < 4; q++) acc[i][j][q] = 0.f;

#pragma unroll 4
    for (int c = 0; c < NC; ++c) {
        // produce chunk c+2 (stage (c+2)%4): WAR-gated on consumption of c-2
        const int pc = c + 2;
        if (pc < NC) {
            const int ps = pc & 3, pj = pc >> 2;
            if (pj > 0)
                mbar_wait(sb + MB_BASE + (uint32_t)ps * 16 + 8, (pj - 1) & 1);
            load_stage(sb, ps, pc, tid, m0, n0, Xhi, Xlo, Whi, Wlo);
        }

        // consume chunk c
        const int s = c & 3, j = c >> 2;
        mbar_wait(sb + MB_BASE + (uint32_t)s * 16, j & 1);
        const uint32_t st = sb + (uint32_t)s * STAGE_BYTES;

        uint32_t wh[8], wl[8];
#pragma unroll
        for (int nfp = 0; nfp < 2; nfp++) {
            uint32_t bo = b_base + (uint32_t)(nfp * 16 * ROWB);
            ldsm4(wh + 4 * nfp, st + OFF_BHI + bo);
            ldsm4(wl + 4 * nfp, st + OFF_BLO + bo);
        }
        uint32_t fxh[4][4], fxl[4][4];
#pragma unroll
        for (int mf = 0; mf < 4; mf++) {
            uint32_t ao = a_base + (uint32_t)(mf * 16 * ROWB);
            ldsm4(fxh[mf], st + OFF_AHI + ao);
            ldsm4(fxl[mf], st + OFF_ALO + ao);
        }
        // buffer free for refill as soon as fragments are in registers
        if (lane == 0)
            mbar_arrive(sb + MB_BASE + (uint32_t)s * 16 + 8);

        // term-major: 16 independent HMMAs per pass
#pragma unroll
        for (int mf = 0; mf < 4; mf++)
#pragma unroll
            for (int nf = 0; nf < 4; nf++)
                mma16816(acc[mf][nf], fxh[mf], wh + 2 * nf);
#pragma unroll
        for (int mf = 0; mf < 4; mf++)
#pragma unroll
            for (int nf = 0; nf < 4; nf++)
                mma16816(acc[mf][nf], fxl[mf], wh + 2 * nf);
#pragma unroll
        for (int mf = 0; mf < 4; mf++)
#pragma unroll
            for (int nf = 0; nf < 4; nf++)
                mma16816(acc[mf][nf], fxh[mf], wl + 2 * nf);
    }

    // epilogue
#pragma unroll
    for (int mf = 0; mf < 4; mf++) {
#pragma unroll
        for (int nf = 0; nf < 4; nf++) {
            const float* c = acc[mf][nf];
            int row0 = m0 + wm * 64 + mf * 16 + (lane >> 2);
            int row1 = row0 + 8;
            int n = n0 + wn * 32 + nf * 8 + 2 * (lane & 3);
            float bn0 = bias[n], bn1 = bias[n + 1];
            size_t o0 = (size_t)row0 * DIMV + n;
            size_t o1 = (size_t)row1 * DIMV + n;
            if (mode == 0) {
                float v00 = fmaxf(c[0] + bn0, 0.f), v01 = fmaxf(c[1] + bn1, 0.f);
                float v10 = fmaxf(c[2] + bn0, 0.f), v11 = fmaxf(c[3] + bn1, 0.f);
                __nv_bfloat162 h2, l2;
                h2.x = __float2bfloat16(v00); l2.x = __float2bfloat16(v00 - __bfloat162float(h2.x));
                h2.y = __float2bfloat16(v01); l2.y = __float2bfloat16(v01 - __bfloat162float(h2.y));
                *(__nv_bfloat162*)(Ohi + o0) = h2;
                *(__nv_bfloat162*)(Olo + o0) = l2;
                h2.x = __float2bfloat16(v10); l2.x = __float2bfloat16(v10 - __bfloat162float(h2.x));
                h2.y = __float2bfloat16(v11); l2.y = __float2bfloat16(v11 - __bfloat162float(h2.y));
                *(__nv_bfloat162*)(Ohi + o1) = h2;
                *(__nv_bfloat162*)(Olo + o1) = l2;
            } else {
                float2 hv0, hv1;
                if (hinf) {
                    hv0 = *(const float2*)(hinf + o0);
                    hv1 = *(const float2*)(hinf + o1);
                } else {
                    __nv_bfloat162 h0 = *(const __nv_bfloat162*)(hinh + o0);
                    __nv_bfloat162 l0 = *(const __nv_bfloat162*)(hinl + o0);
                    __nv_bfloat162 h1 = *(const __nv_bfloat162*)(hinh + o1);
                    __nv_bfloat162 l1 = *(const __nv_bfloat162*)(hinl + o1);
                    hv0.x = __bfloat162float(h0.x) + __bfloat162float(l0.x);
                    hv0.y = __bfloat162float(h0.y) + __bfloat162float(l0.y);
                    hv1.x = __bfloat162float(h1.x) + __bfloat162float(l1.x);
                    hv1.y = __bfloat162float(h1.y) + __bfloat162float(l1.y);
                }
                float2 r0v; r0v.x = c[0] + bn0 + hv0.x; r0v.y = c[1] + bn1 + hv0.y;
                float2 r1v; r1v.x = c[2] + bn0 + hv1.x; r1v.y = c[3] + bn1 + hv1.y;
                *(float2*)(fout + o0) = r0v;
                *(float2*)(fout + o1) = r1v;
            }
        }
    }
}

// ---------------------------------------------------------------------------
// LayerNorm: reads fp32 t, writes ONLY the bf16 hi/lo pair (activation AND
// residual source for layer 3k+2 -> no fp32 hout stream).
// ---------------------------------------------------------------------------
__global__ __launch_bounds__(256) void ln_kernel(
    const float* __restrict__ t, const float* __restrict__ g,
    const float* __restrict__ bb,
    __nv_bfloat16* __restrict__ Ohi, __nv_bfloat16* __restrict__ Olo)
{
    int row = blockIdx.x;
    int tid = threadIdx.x;
    const float* tr = t + (size_t)row * DIMV;

    float v[4];
#pragma unroll
    for (int i = 0; i < 4; i++) v[i] = tr[tid + 256 * i];

    float s = v[0] + v[1] + v[2] + v[3];
#pragma unroll
    for (int o = 16; o > 0; o >>= 1) s += __shfl_xor_sync(0xffffffffu, s, o);

    __shared__ float red[8];
    int w = tid >> 5, ln = tid & 31;
    if (ln == 0) red[w] = s;
    __syncthreads();
    float tot = 0.f;
#pragma unroll
    for (int i = 0; i < 8; i++) tot += red[i];
    float mu = tot * (1.0f / 1024.0f);

    float sq = 0.f;
#pragma unroll
    for (int i = 0; i < 4; i++) { float d = v[i] - mu; sq += d * d; }
#pragma unroll
    for (int o = 16; o > 0; o >>= 1) sq += __shfl_xor_sync(0xffffffffu, sq, o);
    __syncthreads();
    if (ln == 0) red[w] = sq;
    __syncthreads();
    float vtot = 0.f;
#pragma unroll
    for (int i = 0; i < 8; i++) vtot += red[i];
    float rs = rsqrtf(vtot * (1.0f / 1024.0f) + 1e-5f);

#pragma unroll
    for (int i = 0; i < 4; i++) {
        int col = tid + 256 * i;
        float o = (v[i] - mu) * rs * g[col] + bb[col];
        size_t idx = (size_t)row * DIMV + col;
        __nv_bfloat16 h = __float2bfloat16(o);
        Ohi[idx] = h;
        Olo[idx] = __float2bfloat16(o - __bfloat162float(h));
    }
}

// ---------------------------------------------------------------------------
// Host
// ---------------------------------------------------------------------------
extern "C" void kernel_launch(void* const* d_in, const int* in_sizes, int n_in,
                              void* d_out, int out_size)
{
    const float* x      = (const float*)d_in[0];
    const int*   qw     = (const int*)d_in[1];
    const float* scales = (const float*)d_in[2];
    const float* bias   = (const float*)d_in[3];
    const float* la     = (const float*)d_in[4];
    const float* lb     = (const float*)d_in[5];
    const float* lng    = (const float*)d_in[6];
    const float* lnb    = (const float*)d_in[7];
    float* out = (float*)d_out;

    void* p;
    cudaGetSymbolAddress(&p, g_Whi);  __nv_bfloat16* Whi  = (__nv_bfloat16*)p;
    cudaGetSymbolAddress(&p, g_Wlo);  __nv_bfloat16* Wlo  = (__nv_bfloat16*)p;
    cudaGetSymbolAddress(&p, g_ahi0); __nv_bfloat16* Ahi0 = (__nv_bfloat16*)p;
    cudaGetSymbolAddress(&p, g_alo0); __nv_bfloat16* Alo0 = (__nv_bfloat16*)p;
    cudaGetSymbolAddress(&p, g_ahi1); __nv_bfloat16* Ahi1 = (__nv_bfloat16*)p;
    cudaGetSymbolAddress(&p, g_alo1); __nv_bfloat16* Alo1 = (__nv_bfloat16*)p;
    cudaGetSymbolAddress(&p, g_ybuf); float* Ybuf = (float*)p;
    cudaGetSymbolAddress(&p, g_h);
    __nv_bfloat16* Hhi = (__nv_bfloat16*)p;                       // first half of g_h
    __nv_bfloat16* Hlo = (__nv_bfloat16*)p + (size_t)BV * DIMV;   // second half

    cudaFuncSetAttribute(gemm_kernel,
                         cudaFuncAttributeMaxDynamicSharedMemorySize, SMEM_TOTAL);

    prep_w_kernel<<<dim3(16, 16, NL), 256>>>(qw, scales, la, lb, Whi, Wlo);
    // x split goes into the H pair (input of layer 0)
    split_x_kernel<<<(BV * DIMV) / 256, 256>>>(x, Hhi, Hlo);

    for (int l = 0; l < NL; l++) {
        const __nv_bfloat16* wh = Whi + (size_t)l * DIMV * DIMV;
        const __nv_bfloat16* wl = Wlo + (size_t)l * DIMV * DIMV;
        const float* bl = bias + (size_t)l * DIMV;
        const int j = l % 3;

        // layer inputs: 3k <- H pair; 3k+1 <- act0; 3k+2 <- act1
        const __nv_bfloat16* xhi = (j == 0) ? Hhi : (j == 1 ? Ahi0 : Ahi1);
        const __nv_bfloat16* xlo = (j == 0) ? Hlo : (j == 1 ? Alo0 : Alo1);

        if (j != 2) {
            __nv_bfloat16* ohi = (j == 0) ? Ahi0 : Ahi1;
            __nv_bfloat16* olo = (j == 0) ? Alo0 : Alo1;
            gemm_kernel<<<dim3(DIMV / TN, BV / TM), NTHR, SMEM_TOTAL>>>(
                xhi, xlo, wh, wl, bl, 0,
                nullptr, nullptr, nullptr, nullptr, ohi, olo);
        } else {
            // residual: block 0 uses original fp32 x; later blocks use H pair
            const float* hinf = (l == 2) ? x : nullptr;
            const __nv_bfloat16* hinh = (l == 2) ? nullptr : Hhi;
            const __nv_bfloat16* hinl = (l == 2) ? nullptr : Hlo;
            float* fo = (l == NL - 1) ? out : Ybuf;
            gemm_kernel<<<dim3(DIMV / TN, BV / TM), NTHR, SMEM_TOTAL>>>(
                xhi, xlo, wh, wl, bl, 1,
                hinf, hinh, hinl, fo, nullptr, nullptr);
            if (l != NL - 1) {
                int blk = l / 3;
                ln_kernel<<<BV, 256>>>(Ybuf, lng + (size_t)blk * DIMV,
                                       lnb + (size_t)blk * DIMV, Hhi, Hlo);
            }
        }
    }
}

// round 12
// speedup vs baseline: 1.0282x; 1.0015x over previous
#include <cuda_runtime.h>
#include <cuda_bf16.h>
#include <cstdint>
#include <cstddef>

// ---------------------------------------------------------------------------
// QLoRABigNet, mma.sync path (tcgen05 unavailable at compute_103 PTX target).
// 18 layers of y = x @ W_eff^T + bias (+relu / +residual / LN).
// W_eff = dequant_int4 + lora_b@lora_a precomputed; split-bf16 3-MMA numerics.
// R12: R11 + (a) LDSM/MMA interleave (hi-batch -> pass1 -> lo-batch),
//      (b) relaxed producer empty-wait (async-proxy only after wait),
//      (c) hoisted producer global pointers (ALU cut).
// ---------------------------------------------------------------------------

#define NL    18
#define DIMV  1024
#define BV    32768
#define NGRP  64

#define TM 128
#define TN 128
#define KC16 16
#define NC (DIMV / KC16)         // 64 chunks
#define NSTAGE 4
#define NTHR 256

#define ROWB 48                  // 32B data + 16B pad, conflict-free ldsm
#define OFF_AHI 0
#define OFF_ALO 6144             // 128*48
#define OFF_BHI 12288
#define OFF_BLO 18432
#define STAGE_BYTES 24576
#define MB_BASE (NSTAGE * STAGE_BYTES)      // 98304
#define SMEM_TOTAL (MB_BASE + 128)          // 98432 -> 2 CTAs/SM

// ---- scratch (device globals: allocation-free contract) --------------------
__device__ __nv_bfloat16 g_Whi[(size_t)NL * DIMV * DIMV];
__device__ __nv_bfloat16 g_Wlo[(size_t)NL * DIMV * DIMV];
__device__ __nv_bfloat16 g_ahi0[(size_t)BV * DIMV];
__device__ __nv_bfloat16 g_alo0[(size_t)BV * DIMV];
__device__ __nv_bfloat16 g_ahi1[(size_t)BV * DIMV];
__device__ __nv_bfloat16 g_alo1[(size_t)BV * DIMV];
__device__ float         g_ybuf[(size_t)BV * DIMV];
__device__ float         g_h[(size_t)BV * DIMV];   // carved: Hhi | Hlo (bf16)

// ---------------------------------------------------------------------------
// PTX helpers
// ---------------------------------------------------------------------------
__device__ __forceinline__ void ldsm4(uint32_t* r, uint32_t a) {
    asm volatile("ldmatrix.sync.aligned.m8n8.x4.shared.b16 {%0,%1,%2,%3}, [%4];\n"
                 : "=r"(r[0]), "=r"(r[1]), "=r"(r[2]), "=r"(r[3]) : "r"(a));
}
__device__ __forceinline__ void mma16816(float* c, const uint32_t* a, const uint32_t* b) {
    asm volatile(
        "mma.sync.aligned.m16n8k16.row.col.f32.bf16.bf16.f32 "
        "{%0,%1,%2,%3}, {%4,%5,%6,%7}, {%8,%9}, {%0,%1,%2,%3};\n"
        : "+f"(c[0]), "+f"(c[1]), "+f"(c[2]), "+f"(c[3])
        : "r"(a[0]), "r"(a[1]), "r"(a[2]), "r"(a[3]), "r"(b[0]), "r"(b[1]));
}
__device__ __forceinline__ void cpa16(uint32_t dst, const void* src) {
    asm volatile("cp.async.cg.shared.global [%0], [%1], 16;" :: "r"(dst), "l"(src));
}
__device__ __forceinline__ void mbar_init(uint32_t addr, uint32_t cnt) {
    asm volatile("mbarrier.init.shared.b64 [%0], %1;" :: "r"(addr), "r"(cnt) : "memory");
}
__device__ __forceinline__ void mbar_arrive(uint32_t addr) {
    asm volatile("mbarrier.arrive.shared.b64 _, [%0];" :: "r"(addr) : "memory");
}
__device__ __forceinline__ void cp_arrive_noinc(uint32_t addr) {
    asm volatile("cp.async.mbarrier.arrive.noinc.shared.b64 [%0];" :: "r"(addr) : "memory");
}
__device__ __forceinline__ void mbar_wait(uint32_t addr, uint32_t parity) {
    asm volatile(
        "{\n .reg .pred P;\n"
        "W%=:\n mbarrier.try_wait.parity.acquire.cta.shared::cta.b64 P, [%0], %1, 0x989680;\n"
        " @P bra D%=;\n bra W%=;\nD%=:\n}"
        :: "r"(addr), "r"(parity) : "memory");
}
// Producer-side wait: post-wait SMEM writes are cp.async (async proxy) only,
// ordered by their own mechanism -> relaxed is sufficient.
__device__ __forceinline__ void mbar_wait_relaxed(uint32_t addr, uint32_t parity) {
    asm volatile(
        "{\n .reg .pred P;\n"
        "W%=:\n mbarrier.try_wait.parity.relaxed.cta.shared::cta.b64 P, [%0], %1, 0x989680;\n"
        " @P bra D%=;\n bra W%=;\nD%=:\n}"
        :: "r"(addr), "r"(parity) : "memory");
}

// ---------------------------------------------------------------------------
// Prepass: W_eff = qw*scale + B@A, split bf16 hi/lo. (validated R3/R5-R11)
// ---------------------------------------------------------------------------
__global__ __launch_bounds__(256) void prep_w_kernel(
    const int* __restrict__ qw, const float* __restrict__ sc,
    const float* __restrict__ la, const float* __restrict__ lb,
    __nv_bfloat16* __restrict__ Whi, __nv_bfloat16* __restrict__ Wlo)
{
    int l  = blockIdx.z;
    int o0 = blockIdx.y * 64;
    int k0 = blockIdx.x * 64;
    int tid = threadIdx.x;

    __shared__ float sLb[64][32];
    __shared__ float sLa[32][64];

    const float* lbp = lb + (size_t)l * DIMV * 32;
    const float* lap = la + (size_t)l * 32 * DIMV;

#pragma unroll
    for (int i = 0; i < 8; i++) {
        int off = tid + i * 256;
        int o = off >> 5, r = off & 31;
        sLb[o][r] = lbp[(size_t)(o0 + o) * 32 + r];
        int r2 = off >> 6, k = off & 63;
        sLa[r2][k] = lap[(size_t)r2 * DIMV + k0 + k];
    }
    __syncthreads();

    int to = tid >> 4, tk = tid & 15;
    float m[4][4];
#pragma unroll
    for (int i = 0; i < 4; i++)
#pragma unroll
        for (int j = 0; j < 4; j++) m[i][j] = 0.f;

#pragma unroll 8
    for (int r = 0; r < 32; r++) {
        float av[4], bv[4];
#pragma unroll
        for (int j = 0; j < 4; j++) av[j] = sLa[r][tk * 4 + j];
#pragma unroll
        for (int i = 0; i < 4; i++) bv[i] = sLb[to * 4 + i][r];
#pragma unroll
        for (int i = 0; i < 4; i++)
#pragma unroll
            for (int j = 0; j < 4; j++) m[i][j] += bv[i] * av[j];
    }

#pragma unroll
    for (int i = 0; i < 4; i++) {
        int o = o0 + to * 4 + i;
        const int*   qrow = qw + ((size_t)l * DIMV + o) * DIMV + k0;
        const float* srow = sc + ((size_t)l * DIMV + o) * NGRP;
#pragma unroll
        for (int j = 0; j < 4; j++) {
            int k = k0 + tk * 4 + j;
            float wv = (float)qrow[tk * 4 + j] * srow[k >> 4] + m[i][j];
            size_t idx = ((size_t)l * DIMV + o) * DIMV + k;
            __nv_bfloat16 h = __float2bfloat16(wv);
            Whi[idx] = h;
            Wlo[idx] = __float2bfloat16(wv - __bfloat162float(h));
        }
    }
}

__global__ __launch_bounds__(256) void split_x_kernel(
    const float* __restrict__ x, __nv_bfloat16* __restrict__ hi,
    __nv_bfloat16* __restrict__ lo)
{
    size_t i = (size_t)blockIdx.x * 256 + threadIdx.x;
    float v = x[i];
    __nv_bfloat16 h = __float2bfloat16(v);
    hi[i] = h;
    lo[i] = __float2bfloat16(v - __bfloat162float(h));
}

// ---------------------------------------------------------------------------
// GEMM: C[BV,DIMV] = X @ W^T. grid (8, 256), 256 threads, 8 warps (2x4),
// warp tile 64x32. mbarrier 4-stage ring over K=16 chunks, 2 CTAs/SM.
// mode 0: out = relu(acc+bias) -> bf16 hi/lo pair
// mode 1: out = acc+bias+res -> fp32; res = hinf (fp32) if non-null,
//         else hi+lo from (hinh, hinl) bf16 pair.
// ---------------------------------------------------------------------------
__global__ __launch_bounds__(NTHR, 2) void gemm_kernel(
    const __nv_bfloat16* __restrict__ Xhi, const __nv_bfloat16* __restrict__ Xlo,
    const __nv_bfloat16* __restrict__ Whi, const __nv_bfloat16* __restrict__ Wlo,
    const float* __restrict__ bias, int mode,
    const float* __restrict__ hinf,
    const __nv_bfloat16* __restrict__ hinh, const __nv_bfloat16* __restrict__ hinl,
    float* __restrict__ fout,
    __nv_bfloat16* __restrict__ Ohi, __nv_bfloat16* __restrict__ Olo)
{
    extern __shared__ __align__(128) char smem[];
    const uint32_t sb = (uint32_t)__cvta_generic_to_shared(smem);

    const int tid = threadIdx.x, warp = tid >> 5, lane = tid & 31;
    const int wm = warp >> 2, wn = warp & 3;         // 2 x 4 warp grid, 64x32 tile
    const int m0 = blockIdx.y * TM, n0 = blockIdx.x * TN;

    // barriers: full[s] at MB_BASE + s*16, empty[s] at +8
    if (tid == 0) {
#pragma unroll
        for (int s = 0; s < NSTAGE; s++) {
            mbar_init(sb + MB_BASE + s * 16, NTHR);  // full: one noinc-arrive per thread
            mbar_init(sb + MB_BASE + s * 16 + 8, 8); // empty: one arrive per warp
        }
    }
    __syncthreads();

    // producer per-thread layout (hoisted out of chunk loop)
    const int prow = tid >> 1, pseg = tid & 1;
    const uint32_t poff = (uint32_t)(prow * ROWB + pseg * 16);
    const __nv_bfloat16* pXh = Xhi + (size_t)(m0 + prow) * DIMV + pseg * 8;
    const __nv_bfloat16* pXl = Xlo + (size_t)(m0 + prow) * DIMV + pseg * 8;
    const __nv_bfloat16* pWh = Whi + (size_t)(n0 + prow) * DIMV + pseg * 8;
    const __nv_bfloat16* pWl = Wlo + (size_t)(n0 + prow) * DIMV + pseg * 8;

    // ldmatrix per-lane addressing (bytes, relative to stage base)
    const int mi = lane >> 3, rr = lane & 7;
    const uint32_t a_base = (uint32_t)((wm * 64 + (mi & 1) * 8 + rr) * ROWB
                                       + ((mi >> 1) * 8) * 2);
    const uint32_t b_base = (uint32_t)((wn * 32 + ((lane >> 4) << 3) + (lane & 7)) * ROWB
                                       + (((lane >> 3) & 1) * 8) * 2);

    // producer lambda-equivalent
#define PRODUCE(sidx, cidx)                                                    \
    do {                                                                       \
        const uint32_t _st = sb + (uint32_t)(sidx) * STAGE_BYTES;              \
        const int _k = (cidx) * KC16;                                          \
        cpa16(_st + OFF_AHI + poff, pXh + _k);                                 \
        cpa16(_st + OFF_ALO + poff, pXl + _k);                                 \
        cpa16(_st + OFF_BHI + poff, pWh + _k);                                 \
        cpa16(_st + OFF_BLO + poff, pWl + _k);                                 \
        cp_arrive_noinc(sb + MB_BASE + (uint32_t)(sidx) * 16);                 \
    } while (0)

    // prologue: produce chunks 0,1 into stages 0,1 (produce-ahead distance 2)
    PRODUCE(0, 0);
    PRODUCE(1, 1);

    float acc[4][4][4];
#pragma unroll
    for (int i = 0; i < 4; i++)
#pragma unroll
        for (int j = 0; j < 4; j++)
#pragma unroll
            for (int q = 0; q < 4; q++) acc[i][j][q] = 0.f;

#pragma unroll 4
    for (int c = 0; c < NC; ++c) {
        // produce chunk c+2 (stage (c+2)%4): WAR-gated on consumption of c-2
        const int pc = c + 2;
        if (pc < NC) {
            const int ps = pc & 3, pj = pc >> 2;
            if (pj > 0)
                mbar_wait_relaxed(sb + MB_BASE + (uint32_t)ps * 16 + 8, (pj - 1) & 1);
            PRODUCE(ps, pc);
        }

        // consume chunk c
        const int s = c & 3, j = c >> 2;
        mbar_wait(sb + MB_BASE + (uint32_t)s * 16, j & 1);
        const uint32_t st = sb + (uint32_t)s * STAGE_BYTES;

        // batch 1: hi fragments
        uint32_t wh[8], fxh[4][4];
#pragma unroll
        for (int nfp = 0; nfp < 2; nfp++)
            ldsm4(wh + 4 * nfp, st + OFF_BHI + b_base + (uint32_t)(nfp * 16 * ROWB));
#pragma unroll
        for (int mf = 0; mf < 4; mf++)
            ldsm4(fxh[mf], st + OFF_AHI + a_base + (uint32_t)(mf * 16 * ROWB));

        // pass 1 (hi x hi) overlaps the lo-batch LDSM latency below
#pragma unroll
        for (int mf = 0; mf < 4; mf++)
#pragma unroll
            for (int nf = 0; nf < 4; nf++)
                mma16816(acc[mf][nf], fxh[mf], wh + 2 * nf);

        // batch 2: lo fragments
        uint32_t wl[8], fxl[4][4];
#pragma unroll
        for (int nfp = 0; nfp < 2; nfp++)
            ldsm4(wl + 4 * nfp, st + OFF_BLO + b_base + (uint32_t)(nfp * 16 * ROWB));
#pragma unroll
        for (int mf = 0; mf < 4; mf++)
            ldsm4(fxl[mf], st + OFF_ALO + a_base + (uint32_t)(mf * 16 * ROWB));

        // buffer free for refill once all fragments are in registers
        if (lane == 0)
            mbar_arrive(sb + MB_BASE + (uint32_t)s * 16 + 8);

        // passes 2 and 3
#pragma unroll
        for (int mf = 0; mf < 4; mf++)
#pragma unroll
            for (int nf = 0; nf < 4; nf++)
                mma16816(acc[mf][nf], fxl[mf], wh + 2 * nf);
#pragma unroll
        for (int mf = 0; mf < 4; mf++)
#pragma unroll
            for (int nf = 0; nf < 4; nf++)
                mma16816(acc[mf][nf], fxh[mf], wl + 2 * nf);
    }
#undef PRODUCE

    // epilogue
#pragma unroll
    for (int mf = 0; mf < 4; mf++) {
#pragma unroll
        for (int nf = 0; nf < 4; nf++) {
            const float* c = acc[mf][nf];
            int row0 = m0 + wm * 64 + mf * 16 + (lane >> 2);
            int row1 = row0 + 8;
            int n = n0 + wn * 32 + nf * 8 + 2 * (lane & 3);
            float bn0 = bias[n], bn1 = bias[n + 1];
            size_t o0 = (size_t)row0 * DIMV + n;
            size_t o1 = (size_t)row1 * DIMV + n;
            if (mode == 0) {
                float v00 = fmaxf(c[0] + bn0, 0.f), v01 = fmaxf(c[1] + bn1, 0.f);
                float v10 = fmaxf(c[2] + bn0, 0.f), v11 = fmaxf(c[3] + bn1, 0.f);
                __nv_bfloat162 h2, l2;
                h2.x = __float2bfloat16(v00); l2.x = __float2bfloat16(v00 - __bfloat162float(h2.x));
                h2.y = __float2bfloat16(v01); l2.y = __float2bfloat16(v01 - __bfloat162float(h2.y));
                *(__nv_bfloat162*)(Ohi + o0) = h2;
                *(__nv_bfloat162*)(Olo + o0) = l2;
                h2.x = __float2bfloat16(v10); l2.x = __float2bfloat16(v10 - __bfloat162float(h2.x));
                h2.y = __float2bfloat16(v11); l2.y = __float2bfloat16(v11 - __bfloat162float(h2.y));
                *(__nv_bfloat162*)(Ohi + o1) = h2;
                *(__nv_bfloat162*)(Olo + o1) = l2;
            } else {
                float2 hv0, hv1;
                if (hinf) {
                    hv0 = *(const float2*)(hinf + o0);
                    hv1 = *(const float2*)(hinf + o1);
                } else {
                    __nv_bfloat162 h0 = *(const __nv_bfloat162*)(hinh + o0);
                    __nv_bfloat162 l0 = *(const __nv_bfloat162*)(hinl + o0);
                    __nv_bfloat162 h1 = *(const __nv_bfloat162*)(hinh + o1);
                    __nv_bfloat162 l1 = *(const __nv_bfloat162*)(hinl + o1);
                    hv0.x = __bfloat162float(h0.x) + __bfloat162float(l0.x);
                    hv0.y = __bfloat162float(h0.y) + __bfloat162float(l0.y);
                    hv1.x = __bfloat162float(h1.x) + __bfloat162float(l1.x);
                    hv1.y = __bfloat162float(h1.y) + __bfloat162float(l1.y);
                }
                float2 r0v; r0v.x = c[0] + bn0 + hv0.x; r0v.y = c[1] + bn1 + hv0.y;
                float2 r1v; r1v.x = c[2] + bn0 + hv1.x; r1v.y = c[3] + bn1 + hv1.y;
                *(float2*)(fout + o0) = r0v;
                *(float2*)(fout + o1) = r1v;
            }
        }
    }
}

// ---------------------------------------------------------------------------
// LayerNorm: reads fp32 t, writes ONLY the bf16 hi/lo pair (activation AND
// residual source for layer 3k+2).
// ---------------------------------------------------------------------------
__global__ __launch_bounds__(256) void ln_kernel(
    const float* __restrict__ t, const float* __restrict__ g,
    const float* __restrict__ bb,
    __nv_bfloat16* __restrict__ Ohi, __nv_bfloat16* __restrict__ Olo)
{
    int row = blockIdx.x;
    int tid = threadIdx.x;
    const float* tr = t + (size_t)row * DIMV;

    float v[4];
#pragma unroll
    for (int i = 0; i < 4; i++) v[i] = tr[tid + 256 * i];

    float s = v[0] + v[1] + v[2] + v[3];
#pragma unroll
    for (int o = 16; o > 0; o >>= 1) s += __shfl_xor_sync(0xffffffffu, s, o);

    __shared__ float red[8];
    int w = tid >> 5, ln = tid & 31;
    if (ln == 0) red[w] = s;
    __syncthreads();
    float tot = 0.f;
#pragma unroll
    for (int i = 0; i < 8; i++) tot += red[i];
    float mu = tot * (1.0f / 1024.0f);

    float sq = 0.f;
#pragma unroll
    for (int i = 0; i < 4; i++) { float d = v[i] - mu; sq += d * d; }
#pragma unroll
    for (int o = 16; o > 0; o >>= 1) sq += __shfl_xor_sync(0xffffffffu, sq, o);
    __syncthreads();
    if (ln == 0) red[w] = sq;
    __syncthreads();
    float vtot = 0.f;
#pragma unroll
    for (int i = 0; i < 8; i++) vtot += red[i];
    float rs = rsqrtf(vtot * (1.0f / 1024.0f) + 1e-5f);

#pragma unroll
    for (int i = 0; i < 4; i++) {
        int col = tid + 256 * i;
        float o = (v[i] - mu) * rs * g[col] + bb[col];
        size_t idx = (size_t)row * DIMV + col;
        __nv_bfloat16 h = __float2bfloat16(o);
        Ohi[idx] = h;
        Olo[idx] = __float2bfloat16(o - __bfloat162float(h));
    }
}

// ---------------------------------------------------------------------------
// Host
// ---------------------------------------------------------------------------
extern "C" void kernel_launch(void* const* d_in, const int* in_sizes, int n_in,
                              void* d_out, int out_size)
{
    const float* x      = (const float*)d_in[0];
    const int*   qw     = (const int*)d_in[1];
    const float* scales = (const float*)d_in[2];
    const float* bias   = (const float*)d_in[3];
    const float* la     = (const float*)d_in[4];
    const float* lb     = (const float*)d_in[5];
    const float* lng    = (const float*)d_in[6];
    const float* lnb    = (const float*)d_in[7];
    float* out = (float*)d_out;

    void* p;
    cudaGetSymbolAddress(&p, g_Whi);  __nv_bfloat16* Whi  = (__nv_bfloat16*)p;
    cudaGetSymbolAddress(&p, g_Wlo);  __nv_bfloat16* Wlo  = (__nv_bfloat16*)p;
    cudaGetSymbolAddress(&p, g_ahi0); __nv_bfloat16* Ahi0 = (__nv_bfloat16*)p;
    cudaGetSymbolAddress(&p, g_alo0); __nv_bfloat16* Alo0 = (__nv_bfloat16*)p;
    cudaGetSymbolAddress(&p, g_ahi1); __nv_bfloat16* Ahi1 = (__nv_bfloat16*)p;
    cudaGetSymbolAddress(&p, g_alo1); __nv_bfloat16* Alo1 = (__nv_bfloat16*)p;
    cudaGetSymbolAddress(&p, g_ybuf); float* Ybuf = (float*)p;
    cudaGetSymbolAddress(&p, g_h);
    __nv_bfloat16* Hhi = (__nv_bfloat16*)p;                       // first half of g_h
    __nv_bfloat16* Hlo = (__nv_bfloat16*)p + (size_t)BV * DIMV;   // second half

    cudaFuncSetAttribute(gemm_kernel,
                         cudaFuncAttributeMaxDynamicSharedMemorySize, SMEM_TOTAL);

    prep_w_kernel<<<dim3(16, 16, NL), 256>>>(qw, scales, la, lb, Whi, Wlo);
    split_x_kernel<<<(BV * DIMV) / 256, 256>>>(x, Hhi, Hlo);

    for (int l = 0; l < NL; l++) {
        const __nv_bfloat16* wh = Whi + (size_t)l * DIMV * DIMV;
        const __nv_bfloat16* wl = Wlo + (size_t)l * DIMV * DIMV;
        const float* bl = bias + (size_t)l * DIMV;
        const int j = l % 3;

        const __nv_bfloat16* xhi = (j == 0) ? Hhi : (j == 1 ? Ahi0 : Ahi1);
        const __nv_bfloat16* xlo = (j == 0) ? Hlo : (j == 1 ? Alo0 : Alo1);

        if (j != 2) {
            __nv_bfloat16* ohi = (j == 0) ? Ahi0 : Ahi1;
            __nv_bfloat16* olo = (j == 0) ? Alo0 : Alo1;
            gemm_kernel<<<dim3(DIMV / TN, BV / TM), NTHR, SMEM_TOTAL>>>(
                xhi, xlo, wh, wl, bl, 0,
                nullptr, nullptr, nullptr, nullptr, ohi, olo);
        } else {
            const float* hinf = (l == 2) ? x : nullptr;
            const __nv_bfloat16* hinh = (l == 2) ? nullptr : Hhi;
            const __nv_bfloat16* hinl = (l == 2) ? nullptr : Hlo;
            float* fo = (l == NL - 1) ? out : Ybuf;
            gemm_kernel<<<dim3(DIMV / TN, BV / TM), NTHR, SMEM_TOTAL>>>(
                xhi, xlo, wh, wl, bl, 1,
                hinf, hinh, hinl, fo, nullptr, nullptr);
            if (l != NL - 1) {
                int blk = l / 3;
                ln_kernel<<<BV, 256>>>(Ybuf, lng + (size_t)blk * DIMV,
                                       lnb + (size_t)blk * DIMV, Hhi, Hlo);
            }
        }
    }
}